// round 2
// baseline (speedup 1.0000x reference)
#include <cuda_runtime.h>

#define B_    2
#define QLEN  900
#define DIMV  256
#define NH    8
#define HD    32
#define KVLEN 4096
#define GRD   64
#define RPEH  512

// ---------------- scratch (static device globals; no allocation) ----------------
__device__ float d_Kp[B_*NH*KVLEN*HD];   // (b,head,kv,32)
__device__ float d_Vp[B_*NH*KVLEN*HD];   // (b,head,kv,32)
__device__ float d_Qp[B_*NH*QLEN*HD];    // (b,head,q,32), pre-scaled by 1/sqrt(32)
__device__ float d_rpex[B_*NH*QLEN*GRD]; // (b,head,q,w)
__device__ float d_rpey[B_*NH*QLEN*GRD]; // (b,head,q,h)
__device__ float d_ctx[B_*QLEN*DIMV];    // (b,q,256)

// ---------------- tiled fp32 GEMM: C = A(Mx256) @ W(256x256)^T + bias ----------------
// permuted epilogue writes (b,head,row,32) layout for Q/K/V projections.
__global__ void gemm256(const float* __restrict__ A, const float* __restrict__ W,
                        const float* __restrict__ bias, float* __restrict__ C,
                        int M, int rowsPerBatch, float scale, int permuted)
{
    __shared__ float As[16][64];
    __shared__ float Ws[16][64];
    const int bm = blockIdx.x * 64;
    const int bn = blockIdx.y * 64;
    const int tid = threadIdx.x;
    const int tm = (tid >> 4) * 4;
    const int tn = (tid & 15) * 4;
    float acc[4][4];
#pragma unroll
    for (int i = 0; i < 4; i++)
#pragma unroll
        for (int j = 0; j < 4; j++) acc[i][j] = 0.f;

    const int lr = tid >> 2;        // 0..63
    const int lc = (tid & 3) * 4;   // 0,4,8,12

    for (int k0 = 0; k0 < 256; k0 += 16) {
        float4 a4 = make_float4(0.f, 0.f, 0.f, 0.f);
        if (bm + lr < M) a4 = *(const float4*)&A[(bm + lr) * 256 + k0 + lc];
        As[lc + 0][lr] = a4.x; As[lc + 1][lr] = a4.y;
        As[lc + 2][lr] = a4.z; As[lc + 3][lr] = a4.w;
        float4 w4 = *(const float4*)&W[(bn + lr) * 256 + k0 + lc];
        Ws[lc + 0][lr] = w4.x; Ws[lc + 1][lr] = w4.y;
        Ws[lc + 2][lr] = w4.z; Ws[lc + 3][lr] = w4.w;
        __syncthreads();
#pragma unroll
        for (int k = 0; k < 16; k++) {
            float4 av = *(const float4*)&As[k][tm];
            float4 wv = *(const float4*)&Ws[k][tn];
            float a[4] = {av.x, av.y, av.z, av.w};
            float w[4] = {wv.x, wv.y, wv.z, wv.w};
#pragma unroll
            for (int i = 0; i < 4; i++)
#pragma unroll
                for (int j = 0; j < 4; j++) acc[i][j] += a[i] * w[j];
        }
        __syncthreads();
    }

#pragma unroll
    for (int i = 0; i < 4; i++) {
        int row = bm + tm + i;
        if (row >= M) continue;
#pragma unroll
        for (int j = 0; j < 4; j++) {
            int col = bn + tn + j;
            float v = (acc[i][j] + bias[col]) * scale;
            if (permuted) {
                int b = row / rowsPerBatch;
                int r = row - b * rowsPerBatch;
                int head = col >> 5;
                int d = col & 31;
                C[((b * NH + head) * rowsPerBatch + r) * HD + d] = v;
            } else {
                C[row * 256 + col] = v;
            }
        }
    }
}

// ---------------- RPE MLP: per (b,q,axis) block ----------------
// hidden[j] = relu(w1[j][0]*d0 + w1[j][1]*d1 + b1[j]); out[head,p] = sum_j hidden*w2[head][j]
__global__ void rpe_kernel(const float* __restrict__ refpts,
                           const float* __restrict__ w1, const float* __restrict__ b1,
                           const float* __restrict__ w2, float* __restrict__ out, int axis)
{
    __shared__ float2 w1s[RPEH];
    __shared__ float  b1s[RPEH];
    __shared__ float  w2s[RPEH * NH]; // [j][head]

    const int q = blockIdx.x;
    const int b = blockIdx.y;
    const int tid = threadIdx.x;

    for (int i = tid; i < RPEH; i += 256) {
        w1s[i] = make_float2(w1[i * 2], w1[i * 2 + 1]);
        b1s[i] = b1[i];
    }
    for (int i = tid; i < RPEH * NH; i += 256) {
        int j = i >> 3, h = i & 7;
        w2s[i] = w2[h * RPEH + j];
    }

    const float* rp = refpts + (b * QLEN + q) * 4;
    const float c = rp[axis];
    const float s = rp[2 + axis];
    const float lo = (c - 0.5f * s) * 1024.0f;  // grid(64) * stride(16)
    const float hi = (c + 0.5f * s) * 1024.0f;
    __syncthreads();

    const int p  = tid >> 2;   // position 0..63
    const int qr = tid & 3;    // quarter of hidden dim
    const float px = (p + 0.5f) * 16.0f;
    const float d0 = lo - px;
    const float d1 = hi - px;

    float h8[8];
#pragma unroll
    for (int h = 0; h < 8; h++) h8[h] = 0.f;

#pragma unroll 4
    for (int i = 0; i < 128; i++) {
        int j = qr + i * 4;     // interleaved -> conflict-light
        float2 w = w1s[j];
        float hv = fmaxf(w.x * d0 + w.y * d1 + b1s[j], 0.0f);
        const float4* wr = (const float4*)&w2s[j * 8];
        float4 wa = wr[0], wb = wr[1];
        h8[0] += hv * wa.x; h8[1] += hv * wa.y; h8[2] += hv * wa.z; h8[3] += hv * wa.w;
        h8[4] += hv * wb.x; h8[5] += hv * wb.y; h8[6] += hv * wb.z; h8[7] += hv * wb.w;
    }
#pragma unroll
    for (int m = 1; m <= 2; m <<= 1)
#pragma unroll
        for (int h = 0; h < 8; h++) h8[h] += __shfl_xor_sync(0xffffffffu, h8[h], m);

    if (qr == 0) {
#pragma unroll
        for (int h = 0; h < 8; h++)
            out[((b * NH + h) * QLEN + q) * GRD + p] = h8[h];
    }
}

// ---------------- fused attention with online softmax + decomposed RPE ----------------
// block: 256 threads, 32 queries for one (b,head). KV tile = 64 = one grid row.
__global__ void attn_kernel(const int* __restrict__ mask)
{
    __shared__ float Qs[32][HD];       // 4 KB
    __shared__ float rxs[32][GRD];     // 8 KB
    __shared__ float rys[32][GRD];     // 8 KB
    __shared__ float Ks[64][36];       // 9.2 KB (pad 36 -> conflict-free f4 rows)
    __shared__ float Vs[64][36];       // 9.2 KB
    __shared__ float Ps[32][65];       // 8.3 KB (pad 65)
    __shared__ float msks[64];

    const int bh = blockIdx.y;         // b*8 + head
    const int b  = bh >> 3;
    const int head = bh & 7;
    const int q0 = blockIdx.x * 32;
    const int tid = threadIdx.x;

    // load Q tile (pre-scaled)
    {
        int r = tid >> 3, c = (tid & 7) * 4;
        int q = q0 + r;
        float4 v = make_float4(0.f, 0.f, 0.f, 0.f);
        if (q < QLEN) v = *(const float4*)&d_Qp[(bh * QLEN + q) * HD + c];
        *(float4*)&Qs[r][c] = v;
    }
    // load rpe_x / rpe_y rows for this head
    {
        int r = tid >> 3, c = (tid & 7) * 8;
        int q = q0 + r;
        float4 z = make_float4(0.f, 0.f, 0.f, 0.f);
        if (q < QLEN) {
            const float* px = d_rpex + (bh * QLEN + q) * GRD + c;
            const float* py = d_rpey + (bh * QLEN + q) * GRD + c;
            *(float4*)&rxs[r][c]     = *(const float4*)px;
            *(float4*)&rxs[r][c + 4] = *(const float4*)(px + 4);
            *(float4*)&rys[r][c]     = *(const float4*)py;
            *(float4*)&rys[r][c + 4] = *(const float4*)(py + 4);
        } else {
            *(float4*)&rxs[r][c] = z; *(float4*)&rxs[r][c + 4] = z;
            *(float4*)&rys[r][c] = z; *(float4*)&rys[r][c + 4] = z;
        }
    }
    __syncthreads();

    const int myq = tid >> 3;   // query within tile
    const int g   = tid & 7;    // kv-group / d-group
    float qreg[32];
#pragma unroll
    for (int c = 0; c < 8; c++) {
        float4 v = *(const float4*)&Qs[myq][c * 4];
        qreg[c * 4 + 0] = v.x; qreg[c * 4 + 1] = v.y;
        qreg[c * 4 + 2] = v.z; qreg[c * 4 + 3] = v.w;
    }

    float m_run = -1e30f, l_run = 0.0f;
    float4 acc = make_float4(0.f, 0.f, 0.f, 0.f);

    const float* Kbase = d_Kp + (size_t)bh * KVLEN * HD;
    const float* Vbase = d_Vp + (size_t)bh * KVLEN * HD;
    const int*   mbase = mask + b * KVLEN;

    for (int t = 0; t < 64; t++) {
        // stage K/V tile + mask
        {
            int r = tid >> 2, c = (tid & 3) * 8;
            const float4* kp = (const float4*)&Kbase[(t * 64 + r) * HD + c];
            const float4* vp = (const float4*)&Vbase[(t * 64 + r) * HD + c];
            *(float4*)&Ks[r][c]     = kp[0];
            *(float4*)&Ks[r][c + 4] = kp[1];
            *(float4*)&Vs[r][c]     = vp[0];
            *(float4*)&Vs[r][c + 4] = vp[1];
            if (tid < 64) msks[tid] = -100.0f * (float)mbase[t * 64 + tid];
        }
        __syncthreads();

        // QK^T for 8 kv per thread, + rpe + mask
        float sc[8];
        const float ry = rys[myq][t];   // kv tile == grid row t
#pragma unroll
        for (int i = 0; i < 8; i++) {
            int kv = g + 8 * i;
            float s = 0.f;
#pragma unroll
            for (int c = 0; c < 8; c++) {
                float4 k4 = *(const float4*)&Ks[kv][c * 4];
                s += qreg[c * 4 + 0] * k4.x + qreg[c * 4 + 1] * k4.y
                   + qreg[c * 4 + 2] * k4.z + qreg[c * 4 + 3] * k4.w;
            }
            sc[i] = s + rxs[myq][kv] + ry + msks[kv];
        }

        // online softmax (8-thread group per query)
        float mloc = sc[0];
#pragma unroll
        for (int i = 1; i < 8; i++) mloc = fmaxf(mloc, sc[i]);
        mloc = fmaxf(mloc, __shfl_xor_sync(0xffffffffu, mloc, 1));
        mloc = fmaxf(mloc, __shfl_xor_sync(0xffffffffu, mloc, 2));
        mloc = fmaxf(mloc, __shfl_xor_sync(0xffffffffu, mloc, 4));
        float m_new = fmaxf(m_run, mloc);
        float fac = __expf(m_run - m_new);
        float psum = 0.f;
#pragma unroll
        for (int i = 0; i < 8; i++) {
            float p = __expf(sc[i] - m_new);
            Ps[myq][g + 8 * i] = p;
            psum += p;
        }
        psum += __shfl_xor_sync(0xffffffffu, psum, 1);
        psum += __shfl_xor_sync(0xffffffffu, psum, 2);
        psum += __shfl_xor_sync(0xffffffffu, psum, 4);
        l_run = l_run * fac + psum;
        m_run = m_new;
        acc.x *= fac; acc.y *= fac; acc.z *= fac; acc.w *= fac;
        __syncthreads();

        // P @ V   (thread owns (myq, d = g*4..g*4+3))
#pragma unroll 16
        for (int kv = 0; kv < 64; kv++) {
            float p = Ps[myq][kv];
            float4 v4 = *(const float4*)&Vs[kv][g * 4];
            acc.x += p * v4.x; acc.y += p * v4.y;
            acc.z += p * v4.z; acc.w += p * v4.w;
        }
        __syncthreads();
    }

    int q = q0 + myq;
    if (q < QLEN) {
        float inv = 1.0f / l_run;
        float4 o = make_float4(acc.x * inv, acc.y * inv, acc.z * inv, acc.w * inv);
        *(float4*)&d_ctx[(b * QLEN + q) * DIMV + head * HD + g * 4] = o;
    }
}

// ---------------- launch ----------------
extern "C" void kernel_launch(void* const* d_in, const int* in_sizes, int n_in,
                              void* d_out, int out_size)
{
    const float* hidden = (const float*)d_in[0];
    const float* refpts = (const float*)d_in[1];
    const float* kvst   = (const float*)d_in[2];
    // d_in[3] spatial_shapes (int64) -> constants hardcoded (64,64)
    const int*   amask  = (const int*)d_in[4];
    const float* m1w1 = (const float*)d_in[5];
    const float* m1b1 = (const float*)d_in[6];
    const float* m1w2 = (const float*)d_in[7];
    const float* m2w1 = (const float*)d_in[8];
    const float* m2b1 = (const float*)d_in[9];
    const float* m2w2 = (const float*)d_in[10];
    const float* qw = (const float*)d_in[11];
    const float* qb = (const float*)d_in[12];
    const float* kw = (const float*)d_in[13];
    const float* kb = (const float*)d_in[14];
    const float* vw = (const float*)d_in[15];
    const float* vb = (const float*)d_in[16];
    const float* ow = (const float*)d_in[17];
    const float* ob = (const float*)d_in[18];
    float* out = (float*)d_out;

    float *pK, *pV, *pQ, *pRX, *pRY, *pCTX;
    cudaGetSymbolAddress((void**)&pK,   d_Kp);
    cudaGetSymbolAddress((void**)&pV,   d_Vp);
    cudaGetSymbolAddress((void**)&pQ,   d_Qp);
    cudaGetSymbolAddress((void**)&pRX,  d_rpex);
    cudaGetSymbolAddress((void**)&pRY,  d_rpey);
    cudaGetSymbolAddress((void**)&pCTX, d_ctx);

    dim3 blk(256);
    const float qscale = 0.17677669529663687f;  // 1/sqrt(32)

    gemm256<<<dim3(128, 4), blk>>>(kvst,   kw, kb, pK,   B_ * KVLEN, KVLEN, 1.0f,   1);
    gemm256<<<dim3(128, 4), blk>>>(kvst,   vw, vb, pV,   B_ * KVLEN, KVLEN, 1.0f,   1);
    gemm256<<<dim3(29, 4),  blk>>>(hidden, qw, qb, pQ,   B_ * QLEN,  QLEN,  qscale, 1);
    rpe_kernel<<<dim3(QLEN, B_), blk>>>(refpts, m1w1, m1b1, m1w2, pRX, 0);
    rpe_kernel<<<dim3(QLEN, B_), blk>>>(refpts, m2w1, m2b1, m2w2, pRY, 1);
    attn_kernel<<<dim3(29, B_ * NH), blk>>>(amask);
    gemm256<<<dim3(29, 4),  blk>>>(pCTX,   ow, ob, out,  B_ * QLEN,  QLEN,  1.0f,   0);
}